// round 15
// baseline (speedup 1.0000x reference)
#include <cuda_runtime.h>
#include <cuda_bf16.h>
#include <math.h>

#define H 256
#define SENC 1024
#define NSTEP 256
#define VOCAB 47
#define UPC 8
#define LSTRIDE ((NSTEP + 1) * H)
#define GPL 32
#define RNN_BLOCKS 96
#define ATTN_BLOCKS 128
#define TAGPAD 8   // 32B per tag

// ---------------- device scratch ----------------
__device__ float g_xw1[NSTEP * 1024];            // emb[Y[t]]@W_ih1^T + b_ih1 + b_hh1
__device__ float g_VOutB[H * SENC];              // att_V@outEnc^T + att_b
__device__ __align__(16) float g_Hval[3 * LSTRIDE];          // plain h values
__device__ unsigned g_TagC[3 * (NSTEP + 1) * GPL * TAGPAD];  // per-(layer,t,CTA) tag

__device__ __forceinline__ unsigned tidx(int l, int t, int p) {
    return ((unsigned)(l * (NSTEP + 1) + t) * GPL + p) * TAGPAD;
}

// accurate-enough tanh for attention path (R2/R5-proven)
__device__ __forceinline__ float tanh_poly(float x) {
    float t = x * x;
    float p = fmaf(t, 0.0218694885f, -0.0539682540f);
    p = fmaf(t, p, 0.1333333333f);
    p = fmaf(t, p, -0.3333333333f);
    float y = fmaf(x * t, p, x);
    if (fabsf(x) > 0.5f) y = tanhf(x);
    return y;
}

// ---- tag ops: 4B scalar, acquire/release only on the TAG (data rides plain) ----
__device__ __forceinline__ unsigned ld_acq32(const unsigned* a) {
    unsigned v;
    asm volatile("ld.acquire.gpu.global.u32 %0,[%1];" : "=r"(v) : "l"(a) : "memory");
    return v;
}
__device__ __forceinline__ void st_rel32(unsigned* a, unsigned v) {
    asm volatile("st.release.gpu.global.u32 [%0],%1;" :: "l"(a), "r"(v) : "memory");
}
__device__ __forceinline__ void poll_acq(const unsigned* a, unsigned tag) {
    if (ld_acq32(a) == tag) return;
    while (ld_acq32(a) != tag) __nanosleep(64);
}
__device__ __forceinline__ void poll_acq_sleep(const unsigned* a, unsigned tag) {
    while (ld_acq32(a) != tag) __nanosleep(1000);
}

// ---- packed f32x2 helpers ----
__device__ __forceinline__ unsigned long long f32x2_pack(float lo, float hi) {
    unsigned long long v;
    asm("mov.b64 %0,{%1,%2};" : "=l"(v) : "f"(lo), "f"(hi));
    return v;
}
__device__ __forceinline__ float f32x2_sum(unsigned long long v) {
    float lo, hi;
    asm("mov.b64 {%0,%1},%2;" : "=f"(lo), "=f"(hi) : "l"(v));
    return lo + hi;
}
__device__ __forceinline__ unsigned long long fma2(unsigned long long a,
                                                   unsigned long long b,
                                                   unsigned long long c) {
    unsigned long long d;
    asm("fma.rn.f32x2 %0,%1,%2,%3;" : "=l"(d) : "l"(a), "l"(b), "l"(c));
    return d;
}

// =====================================================================
// Kernel 1: prep — tag clear + init, xw1 GEMM, VOutB GEMM
// blocks 0..255: xw1; 256..511: VOutB; 512..519: tags/init
// =====================================================================
__global__ void __launch_bounds__(256) prep_kernel(
    const int* __restrict__ Y, const float* __restrict__ h0,
    const float* __restrict__ emb, const float* __restrict__ W_ih1,
    const float* __restrict__ b_ih1, const float* __restrict__ b_hh1,
    const float* __restrict__ att_V, const float* __restrict__ att_b,
    const float* __restrict__ outEnc)
{
    int bid = blockIdx.x, tid = threadIdx.x;
    if (bid >= 512) {
        int base = (bid - 512) * 256 + tid;
        for (int i = base; i < 3 * NSTEP * GPL; i += 8 * 256) {
            int l = i / (NSTEP * GPL);
            int rem = i - l * (NSTEP * GPL);
            int t = rem / GPL + 1;
            int p = rem % GPL;
            g_TagC[tidx(l, t, p)] = 0xFFFFFFFFu;
        }
        if (bid == 519) {
            // t=0 values + tags (kernel boundary publishes both)
            g_Hval[0 * LSTRIDE + tid] = h0[0 * H + tid];
            g_Hval[1 * LSTRIDE + tid] = h0[1 * H + tid];
            g_Hval[2 * LSTRIDE + tid] = h0[2 * H + tid];
            if (tid < 3 * GPL) {
                int l = tid / GPL, p = tid % GPL;
                g_TagC[tidx(l, 0, p)] = 0u;
            }
        }
        return;
    }
    __shared__ __align__(16) float As[32][33];
    __shared__ __align__(16) float Bs[32][33];
    int mode = bid >> 8;
    int tb = bid & 255;
    int m0 = (tb & 7) * 32;
    int n0 = (tb >> 3) * 32;
    const float* Bsrc = mode ? outEnc : W_ih1;

    int tm = tid & 31;
    int tn = tid >> 5;
    int ar = tid >> 3, ak = (tid & 7) << 2;

    float acc0 = 0.f, acc1 = 0.f, acc2 = 0.f, acc3 = 0.f;
    for (int k0 = 0; k0 < H; k0 += 32) {
        const float* arow = mode ? (att_V + (m0 + ar) * H) : (emb + Y[m0 + ar] * H);
        float4 a4 = *(const float4*)(arow + k0 + ak);
        As[ar][ak] = a4.x; As[ar][ak + 1] = a4.y; As[ar][ak + 2] = a4.z; As[ar][ak + 3] = a4.w;
        float4 b4 = *(const float4*)(Bsrc + (n0 + ar) * H + k0 + ak);
        Bs[ar][ak] = b4.x; Bs[ar][ak + 1] = b4.y; Bs[ar][ak + 2] = b4.z; Bs[ar][ak + 3] = b4.w;
        __syncthreads();
#pragma unroll
        for (int kk = 0; kk < 32; kk++) {
            float a = As[tm][kk];
            acc0 += a * Bs[tn * 4 + 0][kk];
            acc1 += a * Bs[tn * 4 + 1][kk];
            acc2 += a * Bs[tn * 4 + 2][kk];
            acc3 += a * Bs[tn * 4 + 3][kk];
        }
        __syncthreads();
    }
    int m = m0 + tm;
    float* Cd = mode ? g_VOutB : g_xw1;
    float accs[4] = {acc0, acc1, acc2, acc3};
#pragma unroll
    for (int jj = 0; jj < 4; jj++) {
        int n = n0 + tn * 4 + jj;
        float b = mode ? att_b[m] : (b_ih1[n] + b_hh1[n]);
        Cd[m * 1024 + n] = accs[jj] + b;
    }
}

// =====================================================================
// Kernel 2 (fused): blocks 0..95 = persistent LSTM recurrence,
//                   blocks 96..223 = attention+MLP (2 steps each)
// =====================================================================
__global__ void __launch_bounds__(256) fused_kernel(
    const float* __restrict__ h0, const float* __restrict__ c0,
    const float* __restrict__ Wih2, const float* __restrict__ Whh2,
    const float* __restrict__ bih2, const float* __restrict__ bhh2,
    const float* __restrict__ Wih3, const float* __restrict__ Whh3,
    const float* __restrict__ bih3, const float* __restrict__ bhh3,
    const float* __restrict__ Whh1,
    const float* __restrict__ outEnc, const float* __restrict__ attW,
    const float* __restrict__ attVec,
    const float* __restrict__ w1, const float* __restrict__ b1,
    const float* __restrict__ w2, const float* __restrict__ b2,
    const float* __restrict__ w3, const float* __restrict__ b3,
    float* __restrict__ outp)
{
    __shared__ __align__(16) float sIn[2 * H];   // [x(256) | h_own(256)]
    __shared__ __align__(16) float h2s[2][H];
    __shared__ __align__(16) float wss[2][H];
    __shared__ __align__(16) float avs[H];
    __shared__ __align__(16) float alp[2][SENC];
    __shared__ __align__(16) float red[40];
    __shared__ __align__(16) float vbuf[2][2 * H];
    __shared__ __align__(16) float v1s[2][H];
    __shared__ __align__(16) float v2s[2][H];

    int tid = threadIdx.x, lane = tid & 31, warp = tid >> 5;

    if (blockIdx.x < RNN_BLOCKS) {
        // ============================ RNN ============================
        int l = blockIdx.x >> 5;
        int p = blockIdx.x & 31;
        int u = p * UPC + warp;            // unit owned by this warp

        const float* Wih = (l == 1) ? Wih2 : ((l == 2) ? Wih3 : (const float*)0);
        const float* Whh = (l == 0) ? Whh1 : ((l == 1) ? Whh2 : Whh3);
        const float* bih = (l == 1) ? bih2 : bih3;
        const float* bhh = (l == 1) ? bhh2 : bhh3;

        // weights -> f32x2 regs (R10 layout): row r = gate, [Wih|Whh]
        unsigned long long Wp[4][8];
#pragma unroll
        for (int r = 0; r < 4; r++) {
            int grow = r * H + u;
#pragma unroll
            for (int m = 0; m < 4; m++) {
                float4 w;
                if (m < 2) {
                    if (l == 0) w = make_float4(0.f, 0.f, 0.f, 0.f);
                    else        w = *(const float4*)(Wih + grow * H + 4 * (lane + 32 * m));
                } else {
                    w = *(const float4*)(Whh + grow * H + 4 * (lane + 32 * (m - 2)));
                }
                Wp[r][2 * m]     = f32x2_pack(w.x, w.y);
                Wp[r][2 * m + 1] = f32x2_pack(w.z, w.w);
            }
        }
        float biasreg = 0.f;
        if (l > 0) biasreg = bih[(lane & 3) * H + u] + bhh[(lane & 3) * H + u];

        float creg = 0.f;
        if (lane == 0) creg = c0[l * H + u];
        if (l == 0) sIn[tid] = 0.f;        // x half stays zero for layer 0
        __syncthreads();

        float* ownV = g_Hval + l * LSTRIDE;
        const float* depV = g_Hval + (l - 1) * LSTRIDE;

        for (unsigned t = 1; t <= NSTEP; t++) {
            // ---- phase 1: tag polls (64 threads, 1 word each) ----
            float bstep = 0.f;
            if (tid < 32) {
                poll_acq(&g_TagC[tidx(l, t - 1, tid)], t - 1);
            } else if (tid < 64) {
                if (l > 0) poll_acq(&g_TagC[tidx(l - 1, t, tid - 32)], t);
            } else if (l == 0 && lane < 4) {
                bstep = __ldcg(&g_xw1[(t - 1) * 1024 + lane * H + u]);
            }
            if (l == 0 && tid < 64 && lane < 4)
                bstep = __ldcg(&g_xw1[(t - 1) * 1024 + lane * H + u]);
            __syncthreads();
            // ---- phase 2: vector bulk gather (tags ordered the data) ----
            if (tid < 64) {
                float4 v = __ldcg((const float4*)(ownV + (t - 1) * H + 4 * tid));
                *(float4*)&sIn[H + 4 * tid] = v;
            } else if (tid < 128 && l > 0) {
                float4 v = __ldcg((const float4*)(depV + t * H + 4 * (tid - 64)));
                *(float4*)&sIn[4 * (tid - 64)] = v;
            }
            __syncthreads();

            // ---- phase 3: matvec (4 gates, packed f32x2) ----
            unsigned long long acc0 = 0ULL, acc1 = 0ULL, acc2 = 0ULL, acc3 = 0ULL;
#pragma unroll
            for (int m = 0; m < 4; m++) {
                float4 x = *(const float4*)(sIn + 4 * (lane + 32 * m));
                unsigned long long xlo = f32x2_pack(x.x, x.y);
                unsigned long long xhi = f32x2_pack(x.z, x.w);
                acc0 = fma2(Wp[0][2 * m], xlo, acc0); acc0 = fma2(Wp[0][2 * m + 1], xhi, acc0);
                acc1 = fma2(Wp[1][2 * m], xlo, acc1); acc1 = fma2(Wp[1][2 * m + 1], xhi, acc1);
                acc2 = fma2(Wp[2][2 * m], xlo, acc2); acc2 = fma2(Wp[2][2 * m + 1], xhi, acc2);
                acc3 = fma2(Wp[3][2 * m], xlo, acc3); acc3 = fma2(Wp[3][2 * m + 1], xhi, acc3);
            }
            float s0 = f32x2_sum(acc0), s1 = f32x2_sum(acc1);
            float s2 = f32x2_sum(acc2), s3 = f32x2_sum(acc3);
#pragma unroll
            for (int off = 16; off > 0; off >>= 1) {
                s0 += __shfl_xor_sync(0xffffffffu, s0, off);
                s1 += __shfl_xor_sync(0xffffffffu, s1, off);
                s2 += __shfl_xor_sync(0xffffffffu, s2, off);
                s3 += __shfl_xor_sync(0xffffffffu, s3, off);
            }
            // lanes 0..3: activations of gates i,f,g,o in parallel
            float sv = (lane == 1) ? s1 : (lane == 2) ? s2 : (lane == 3) ? s3 : s0;
            float raw = sv + ((l == 0) ? bstep : biasreg);
            float kk = (lane == 2) ? 2.0f : 1.0f;
            float e = __expf(-kk * raw);
            float sg = __fdividef(1.0f, 1.0f + e);
            float act = (lane == 2) ? fmaf(2.0f, sg, -1.0f) : sg;   // tanh = 2*sig(2x)-1
            float fg = __shfl_sync(0xffffffffu, act, 1);
            float gg = __shfl_sync(0xffffffffu, act, 2);
            float og = __shfl_sync(0xffffffffu, act, 3);
            if (lane == 0) {
                float c = fmaf(fg, creg, act * gg);
                float e2 = __expf(-2.0f * c);
                float th = fmaf(2.0f, __fdividef(1.0f, 1.0f + e2), -1.0f);
                float h = og * th;
                creg = c;
                __stcg(&ownV[t * H + u], h);          // plain data store
            }
            __syncthreads();                           // all 8 unit-stores done
            if (tid == 0) st_rel32(&g_TagC[tidx(l, t, p)], t);   // release tag
        }
        return;
    }

    // ============================ ATTENTION + MLP ============================
    int t0 = (blockIdx.x - RNN_BLOCKS) * 2;

    avs[tid] = attVec[tid];
    if (tid < 32)      poll_acq_sleep(&g_TagC[tidx(2, t0 + 1, tid)], (unsigned)(t0 + 1));
    else if (tid < 64) poll_acq_sleep(&g_TagC[tidx(2, t0 + 2, tid - 32)], (unsigned)(t0 + 2));
    __syncthreads();
    h2s[0][tid] = __ldcg(&g_Hval[2 * LSTRIDE + (t0 + 1) * H + tid]);
    h2s[1][tid] = __ldcg(&g_Hval[2 * LSTRIDE + (t0 + 2) * H + tid]);
    __syncthreads();

    {
        float s0 = 0.f, s1 = 0.f;
        const float4* wr = (const float4*)(attW + tid * H);
        const float4* x0 = (const float4*)h2s[0];
        const float4* x1 = (const float4*)h2s[1];
#pragma unroll 8
        for (int k = 0; k < 64; k++) {
            float4 w = wr[k], a = x0[k], b = x1[k];
            s0 += w.x * a.x + w.y * a.y + w.z * a.z + w.w * a.w;
            s1 += w.x * b.x + w.y * b.y + w.z * b.z + w.w * b.w;
        }
        wss[0][tid] = s0; wss[1][tid] = s1;
    }
    __syncthreads();

    float e00 = 0.f, e01 = 0.f, e02 = 0.f, e03 = 0.f;
    float e10 = 0.f, e11 = 0.f, e12 = 0.f, e13 = 0.f;
    const float4* vb = (const float4*)g_VOutB;
#pragma unroll 4
    for (int h = 0; h < H; h++) {
        float a = avs[h], w0v = wss[0][h], w1v = wss[1][h];
        float4 v4 = vb[h * (SENC / 4) + tid];
        e00 = fmaf(a, tanh_poly(w0v + v4.x), e00);
        e01 = fmaf(a, tanh_poly(w0v + v4.y), e01);
        e02 = fmaf(a, tanh_poly(w0v + v4.z), e02);
        e03 = fmaf(a, tanh_poly(w0v + v4.w), e03);
        e10 = fmaf(a, tanh_poly(w1v + v4.x), e10);
        e11 = fmaf(a, tanh_poly(w1v + v4.y), e11);
        e12 = fmaf(a, tanh_poly(w1v + v4.z), e12);
        e13 = fmaf(a, tanh_poly(w1v + v4.w), e13);
    }

    float mx0 = fmaxf(fmaxf(e00, e01), fmaxf(e02, e03));
    float mx1 = fmaxf(fmaxf(e10, e11), fmaxf(e12, e13));
#pragma unroll
    for (int off = 16; off > 0; off >>= 1) {
        mx0 = fmaxf(mx0, __shfl_xor_sync(0xffffffffu, mx0, off));
        mx1 = fmaxf(mx1, __shfl_xor_sync(0xffffffffu, mx1, off));
    }
    if (lane == 0) { red[warp] = mx0; red[8 + warp] = mx1; }
    __syncthreads();
    if (tid == 0) {
        float m0 = red[0], m1 = red[8];
#pragma unroll
        for (int i = 1; i < 8; i++) { m0 = fmaxf(m0, red[i]); m1 = fmaxf(m1, red[8 + i]); }
        red[32] = m0; red[33] = m1;
    }
    __syncthreads();
    mx0 = red[32]; mx1 = red[33];
    float x00 = __expf(e00 - mx0), x01 = __expf(e01 - mx0);
    float x02 = __expf(e02 - mx0), x03 = __expf(e03 - mx0);
    float x10 = __expf(e10 - mx1), x11 = __expf(e11 - mx1);
    float x12 = __expf(e12 - mx1), x13 = __expf(e13 - mx1);
    float sm0 = x00 + x01 + x02 + x03;
    float sm1 = x10 + x11 + x12 + x13;
#pragma unroll
    for (int off = 16; off > 0; off >>= 1) {
        sm0 += __shfl_xor_sync(0xffffffffu, sm0, off);
        sm1 += __shfl_xor_sync(0xffffffffu, sm1, off);
    }
    if (lane == 0) { red[16 + warp] = sm0; red[24 + warp] = sm1; }
    __syncthreads();
    if (tid == 0) {
        float s0 = 0.f, s1 = 0.f;
#pragma unroll
        for (int i = 0; i < 8; i++) { s0 += red[16 + i]; s1 += red[24 + i]; }
        red[34] = 1.0f / s0;
        red[35] = 1.0f / s1;
    }
    __syncthreads();
    float inv0 = red[34], inv1 = red[35];
    alp[0][4 * tid + 0] = x00 * inv0; alp[0][4 * tid + 1] = x01 * inv0;
    alp[0][4 * tid + 2] = x02 * inv0; alp[0][4 * tid + 3] = x03 * inv0;
    alp[1][4 * tid + 0] = x10 * inv1; alp[1][4 * tid + 1] = x11 * inv1;
    alp[1][4 * tid + 2] = x12 * inv1; alp[1][4 * tid + 3] = x13 * inv1;
    __syncthreads();

    float c0v = 0.f, c1v = 0.f;
#pragma unroll 4
    for (int s = 0; s < SENC; s++) {
        float v = __ldg(&outEnc[s * H + tid]);
        c0v = fmaf(alp[0][s], v, c0v);
        c1v = fmaf(alp[1][s], v, c1v);
    }
    vbuf[0][tid] = h2s[0][tid]; vbuf[0][H + tid] = c0v;
    vbuf[1][tid] = h2s[1][tid]; vbuf[1][H + tid] = c1v;
    __syncthreads();

    {
        float s0 = b1[tid], s1 = s0;
        const float4* r = (const float4*)(w1 + tid * (2 * H));
        const float4* xa = (const float4*)vbuf[0];
        const float4* xb = (const float4*)vbuf[1];
#pragma unroll 8
        for (int k = 0; k < 128; k++) {
            float4 w = r[k], a = xa[k], b = xb[k];
            s0 += w.x * a.x + w.y * a.y + w.z * a.z + w.w * a.w;
            s1 += w.x * b.x + w.y * b.y + w.z * b.z + w.w * b.w;
        }
        v1s[0][tid] = fmaxf(s0, 0.f);
        v1s[1][tid] = fmaxf(s1, 0.f);
    }
    __syncthreads();
    {
        float s0 = b2[tid], s1 = s0;
        const float4* r = (const float4*)(w2 + tid * H);
        const float4* xa = (const float4*)v1s[0];
        const float4* xb = (const float4*)v1s[1];
#pragma unroll 8
        for (int k = 0; k < 64; k++) {
            float4 w = r[k], a = xa[k], b = xb[k];
            s0 += w.x * a.x + w.y * a.y + w.z * a.z + w.w * a.w;
            s1 += w.x * b.x + w.y * b.y + w.z * b.z + w.w * b.w;
        }
        v2s[0][tid] = fmaxf(s0, 0.f);
        v2s[1][tid] = fmaxf(s1, 0.f);
    }
    __syncthreads();
    if (tid < VOCAB) {
        float s0 = b3[tid], s1 = s0;
        const float4* r = (const float4*)(w3 + tid * H);
        const float4* xa = (const float4*)v2s[0];
        const float4* xb = (const float4*)v2s[1];
#pragma unroll 8
        for (int k = 0; k < 64; k++) {
            float4 w = r[k], a = xa[k], b = xb[k];
            s0 += w.x * a.x + w.y * a.y + w.z * a.z + w.w * a.w;
            s1 += w.x * b.x + w.y * b.y + w.z * b.z + w.w * b.w;
        }
        outp[(t0 + 0) * VOCAB + tid] = s0;
        outp[(t0 + 1) * VOCAB + tid] = s1;
    }
}

extern "C" void kernel_launch(void* const* d_in, const int* in_sizes, int n_in,
                              void* d_out, int out_size) {
    const int*   Y      = (const int*)d_in[0];
    const float* h0     = (const float*)d_in[1];
    const float* c0     = (const float*)d_in[2];
    const float* outEnc = (const float*)d_in[3];
    const float* emb    = (const float*)d_in[4];
    const float* W_ih1  = (const float*)d_in[5];
    const float* W_hh1  = (const float*)d_in[6];
    const float* b_ih1  = (const float*)d_in[7];
    const float* b_hh1  = (const float*)d_in[8];
    const float* W_ih2  = (const float*)d_in[9];
    const float* W_hh2  = (const float*)d_in[10];
    const float* b_ih2  = (const float*)d_in[11];
    const float* b_hh2  = (const float*)d_in[12];
    const float* W_ih3  = (const float*)d_in[13];
    const float* W_hh3  = (const float*)d_in[14];
    const float* b_ih3  = (const float*)d_in[15];
    const float* b_hh3  = (const float*)d_in[16];
    const float* attVec = (const float*)d_in[17];
    const float* attW   = (const float*)d_in[18];
    const float* attV   = (const float*)d_in[19];
    const float* attB   = (const float*)d_in[20];
    const float* w1     = (const float*)d_in[21];
    const float* b1     = (const float*)d_in[22];
    const float* w2     = (const float*)d_in[23];
    const float* b2     = (const float*)d_in[24];
    const float* w3     = (const float*)d_in[25];
    const float* b3     = (const float*)d_in[26];
    float* outp = (float*)d_out;

    prep_kernel<<<520, 256>>>(Y, h0, emb, W_ih1, b_ih1, b_hh1, attV, attB, outEnc);
    fused_kernel<<<RNN_BLOCKS + ATTN_BLOCKS, 256>>>(
        h0, c0, W_ih2, W_hh2, b_ih2, b_hh2, W_ih3, W_hh3, b_ih3, b_hh3, W_hh1,
        outEnc, attW, attVec, w1, b1, w2, b2, w3, b3, outp);
}

// round 16
// speedup vs baseline: 1.5206x; 1.5206x over previous
#include <cuda_runtime.h>
#include <cuda_bf16.h>
#include <math.h>

#define H 256
#define SENC 1024
#define NSTEP 256
#define VOCAB 47
#define UPC 16               // units per CTA
#define GPL 16               // CTAs per layer
#define LSTRIDE ((NSTEP + 1) * H)
#define RNN_BLOCKS (3 * GPL) // 48
#define ATTN_BLOCKS 128
#define NTHREADS 512

// ---------------- device scratch ----------------
__device__ float g_xw1[NSTEP * 1024];              // emb[Y[t]]@W_ih1^T + b_ih1 + b_hh1
__device__ float g_VOutB[H * SENC];                // att_V@outEnc^T + att_b
__device__ unsigned long long g_Ht64[3 * LSTRIDE]; // packed {tag<<32 | float bits}

// accurate-enough tanh for attention path (R2/R5-proven)
__device__ __forceinline__ float tanh_poly(float x) {
    float t = x * x;
    float p = fmaf(t, 0.0218694885f, -0.0539682540f);
    p = fmaf(t, p, 0.1333333333f);
    p = fmaf(t, p, -0.3333333333f);
    float y = fmaf(x * t, p, x);
    if (fabsf(x) > 0.5f) y = tanhf(x);
    return y;
}

// ---- aligned 8B SCALAR tag word (vector forms tear: R3/R8) ----
__device__ __forceinline__ unsigned long long ld_tag(const unsigned long long* a) {
    unsigned long long w;
    asm volatile("ld.global.cg.b64 %0,[%1];" : "=l"(w) : "l"(a) : "memory");
    return w;
}
__device__ __forceinline__ void store_tag(unsigned long long* a, float v, unsigned tag) {
    unsigned long long w = ((unsigned long long)tag << 32) |
                           (unsigned long long)__float_as_uint(v);
    asm volatile("st.global.cg.b64 [%0],%1;" :: "l"(a), "l"(w) : "memory");
}
// hot poll (rnn): value rides with tag, exponential backoff (R10-proven)
__device__ __forceinline__ float poll_tag_hot(const unsigned long long* a, unsigned tag) {
    unsigned long long w = ld_tag(a);
    unsigned ns = 32;
    while ((unsigned)(w >> 32) != tag) {
        __nanosleep(ns);
        ns = (ns < 256u) ? (ns << 1) : 256u;
        w = ld_tag(a);
    }
    return __uint_as_float((unsigned)w);
}
// cold poll (attn): heavy backoff
__device__ __forceinline__ float poll_tag_sleep(const unsigned long long* a, unsigned tag) {
    unsigned long long w = ld_tag(a);
    while ((unsigned)(w >> 32) != tag) { __nanosleep(1000); w = ld_tag(a); }
    return __uint_as_float((unsigned)w);
}

// ---- packed f32x2 helpers ----
__device__ __forceinline__ unsigned long long f32x2_pack(float lo, float hi) {
    unsigned long long v;
    asm("mov.b64 %0,{%1,%2};" : "=l"(v) : "f"(lo), "f"(hi));
    return v;
}
__device__ __forceinline__ float f32x2_sum(unsigned long long v) {
    float lo, hi;
    asm("mov.b64 {%0,%1},%2;" : "=f"(lo), "=f"(hi) : "l"(v));
    return lo + hi;
}
__device__ __forceinline__ unsigned long long fma2(unsigned long long a,
                                                   unsigned long long b,
                                                   unsigned long long c) {
    unsigned long long d;
    asm("fma.rn.f32x2 %0,%1,%2,%3;" : "=l"(d) : "l"(a), "l"(b), "l"(c));
    return d;
}

// =====================================================================
// Kernel 1: prep — tag clear + init, xw1 GEMM, VOutB GEMM (R10-identical)
// =====================================================================
__global__ void __launch_bounds__(256) prep_kernel(
    const int* __restrict__ Y, const float* __restrict__ h0,
    const float* __restrict__ emb, const float* __restrict__ W_ih1,
    const float* __restrict__ b_ih1, const float* __restrict__ b_hh1,
    const float* __restrict__ att_V, const float* __restrict__ att_b,
    const float* __restrict__ outEnc)
{
    int bid = blockIdx.x, tid = threadIdx.x;
    if (bid >= 512) {
        int base = (bid - 512) * 256 + tid;
        for (int i = base; i < 3 * NSTEP * H; i += 8 * 256) {
            int l = i / (NSTEP * H);
            int rem = i - l * (NSTEP * H);
            int t = rem / H + 1;
            int u = rem % H;
            g_Ht64[l * LSTRIDE + t * H + u] = 0xFFFFFFFF00000000ULL;
        }
        if (bid == 519) {
            store_tag(&g_Ht64[0 * LSTRIDE + tid], h0[0 * H + tid], 0u);
            store_tag(&g_Ht64[1 * LSTRIDE + tid], h0[1 * H + tid], 0u);
            store_tag(&g_Ht64[2 * LSTRIDE + tid], h0[2 * H + tid], 0u);
        }
        return;
    }
    __shared__ __align__(16) float As[32][33];
    __shared__ __align__(16) float Bs[32][33];
    int mode = bid >> 8;
    int tb = bid & 255;
    int m0 = (tb & 7) * 32;
    int n0 = (tb >> 3) * 32;
    const float* Bsrc = mode ? outEnc : W_ih1;

    int tm = tid & 31;
    int tn = tid >> 5;
    int ar = tid >> 3, ak = (tid & 7) << 2;

    float acc0 = 0.f, acc1 = 0.f, acc2 = 0.f, acc3 = 0.f;
    for (int k0 = 0; k0 < H; k0 += 32) {
        const float* arow = mode ? (att_V + (m0 + ar) * H) : (emb + Y[m0 + ar] * H);
        float4 a4 = *(const float4*)(arow + k0 + ak);
        As[ar][ak] = a4.x; As[ar][ak + 1] = a4.y; As[ar][ak + 2] = a4.z; As[ar][ak + 3] = a4.w;
        float4 b4 = *(const float4*)(Bsrc + (n0 + ar) * H + k0 + ak);
        Bs[ar][ak] = b4.x; Bs[ar][ak + 1] = b4.y; Bs[ar][ak + 2] = b4.z; Bs[ar][ak + 3] = b4.w;
        __syncthreads();
#pragma unroll
        for (int kk = 0; kk < 32; kk++) {
            float a = As[tm][kk];
            acc0 += a * Bs[tn * 4 + 0][kk];
            acc1 += a * Bs[tn * 4 + 1][kk];
            acc2 += a * Bs[tn * 4 + 2][kk];
            acc3 += a * Bs[tn * 4 + 3][kk];
        }
        __syncthreads();
    }
    int m = m0 + tm;
    float* Cd = mode ? g_VOutB : g_xw1;
    float accs[4] = {acc0, acc1, acc2, acc3};
#pragma unroll
    for (int jj = 0; jj < 4; jj++) {
        int n = n0 + tn * 4 + jj;
        float b = mode ? att_b[m] : (b_ih1[n] + b_hh1[n]);
        Cd[m * 1024 + n] = accs[jj] + b;
    }
}

// =====================================================================
// Kernel 2 (fused, 512 threads): blocks 0..47 = LSTM (16 CTAs/layer),
//                                blocks 48..175 = attention+MLP
// =====================================================================
__global__ void __launch_bounds__(NTHREADS) fused_kernel(
    const float* __restrict__ h0, const float* __restrict__ c0,
    const float* __restrict__ Wih2, const float* __restrict__ Whh2,
    const float* __restrict__ bih2, const float* __restrict__ bhh2,
    const float* __restrict__ Wih3, const float* __restrict__ Whh3,
    const float* __restrict__ bih3, const float* __restrict__ bhh3,
    const float* __restrict__ Whh1,
    const float* __restrict__ outEnc, const float* __restrict__ attW,
    const float* __restrict__ attVec,
    const float* __restrict__ w1, const float* __restrict__ b1,
    const float* __restrict__ w2, const float* __restrict__ b2,
    const float* __restrict__ w3, const float* __restrict__ b3,
    float* __restrict__ outp)
{
    __shared__ __align__(16) float sIn[2][2 * H];   // [x(256) | h_own(256)] x2
    __shared__ __align__(16) float h2s[2][H];
    __shared__ __align__(16) float wss[2][H];
    __shared__ __align__(16) float avs[H];
    __shared__ __align__(16) float alp[2][SENC];
    __shared__ __align__(16) float red[40];
    __shared__ __align__(16) float vbuf[2][2 * H];
    __shared__ __align__(16) float v1s[2][H];
    __shared__ __align__(16) float v2s[2][H];

    int tid = threadIdx.x, lane = tid & 31, warp = tid >> 5;

    if (blockIdx.x < RNN_BLOCKS) {
        // ============================ RNN ============================
        int l = blockIdx.x >> 4;       // layer 0..2
        int p = blockIdx.x & 15;       // CTA within layer
        int u = p * UPC + warp;        // warp 0..15 -> unit

        const float* Wih = (l == 1) ? Wih2 : ((l == 2) ? Wih3 : (const float*)0);
        const float* Whh = (l == 0) ? Whh1 : ((l == 1) ? Whh2 : Whh3);
        const float* bih = (l == 1) ? bih2 : bih3;
        const float* bhh = (l == 1) ? bhh2 : bhh3;

        // weights -> f32x2 regs (R10 layout): row r = gate, cols [Wih|Whh]
        unsigned long long Wp[4][8];
#pragma unroll
        for (int r = 0; r < 4; r++) {
            int grow = r * H + u;
#pragma unroll
            for (int m = 0; m < 4; m++) {
                float4 w;
                if (m < 2) {
                    if (l == 0) w = make_float4(0.f, 0.f, 0.f, 0.f);
                    else        w = *(const float4*)(Wih + grow * H + 4 * (lane + 32 * m));
                } else {
                    w = *(const float4*)(Whh + grow * H + 4 * (lane + 32 * (m - 2)));
                }
                Wp[r][2 * m]     = f32x2_pack(w.x, w.y);
                Wp[r][2 * m + 1] = f32x2_pack(w.z, w.w);
            }
        }
        float biasreg = 0.f;
        if (l > 0) biasreg = bih[(lane & 3) * H + u] + bhh[(lane & 3) * H + u];

        float creg = 0.f, hreg = 0.f;
        if (lane == 0) {
            creg = c0[l * H + u];
            hreg = h0[l * H + u];
        }
        if (l == 0 && tid < 256) { sIn[0][tid] = 0.f; sIn[1][tid] = 0.f; }
        __syncthreads();

        unsigned long long* ownB = g_Ht64 + l * LSTRIDE;
        const unsigned long long* depB = g_Ht64 + (l - 1) * LSTRIDE;

        for (unsigned t = 1; t <= NSTEP; t++) {
            float* buf = sIn[t & 1];
            float bstep = 0.f;
            if (l == 0 && lane < 4)
                bstep = __ldcg(&g_xw1[(t - 1) * 1024 + lane * H + u]);
            if (lane == 0) buf[H + u] = hreg;        // local unit from register
            // single-word polls, all concurrent (R10 protocol, 1 word/thread)
            if (tid < 256) {
                bool mine = (tid >= p * UPC) && (tid < p * UPC + UPC);
                if (!mine)
                    buf[H + tid] = poll_tag_hot(ownB + (t - 1) * H + tid, t - 1);
            } else if (l > 0) {
                int j = tid - 256;
                buf[j] = poll_tag_hot(depB + t * H + j, t);
            }
            __syncthreads();

            // matvec: 4 gates, packed f32x2 FMA
            unsigned long long acc0 = 0ULL, acc1 = 0ULL, acc2 = 0ULL, acc3 = 0ULL;
#pragma unroll
            for (int m = 0; m < 4; m++) {
                float4 x = *(const float4*)(buf + 4 * (lane + 32 * m));
                unsigned long long xlo = f32x2_pack(x.x, x.y);
                unsigned long long xhi = f32x2_pack(x.z, x.w);
                acc0 = fma2(Wp[0][2 * m], xlo, acc0); acc0 = fma2(Wp[0][2 * m + 1], xhi, acc0);
                acc1 = fma2(Wp[1][2 * m], xlo, acc1); acc1 = fma2(Wp[1][2 * m + 1], xhi, acc1);
                acc2 = fma2(Wp[2][2 * m], xlo, acc2); acc2 = fma2(Wp[2][2 * m + 1], xhi, acc2);
                acc3 = fma2(Wp[3][2 * m], xlo, acc3); acc3 = fma2(Wp[3][2 * m + 1], xhi, acc3);
            }
            float s0 = f32x2_sum(acc0), s1 = f32x2_sum(acc1);
            float s2 = f32x2_sum(acc2), s3 = f32x2_sum(acc3);
#pragma unroll
            for (int off = 16; off > 0; off >>= 1) {
                s0 += __shfl_xor_sync(0xffffffffu, s0, off);
                s1 += __shfl_xor_sync(0xffffffffu, s1, off);
                s2 += __shfl_xor_sync(0xffffffffu, s2, off);
                s3 += __shfl_xor_sync(0xffffffffu, s3, off);
            }
            // lanes 0..3: activations of gates i,f,g,o
            float sv = (lane == 1) ? s1 : (lane == 2) ? s2 : (lane == 3) ? s3 : s0;
            float raw = sv + ((l == 0) ? bstep : biasreg);
            float kk = (lane == 2) ? 2.0f : 1.0f;
            float e = __expf(-kk * raw);
            float sg = __fdividef(1.0f, 1.0f + e);
            float act = (lane == 2) ? fmaf(2.0f, sg, -1.0f) : sg;   // tanh = 2*sig(2x)-1
            float fg = __shfl_sync(0xffffffffu, act, 1);
            float gg = __shfl_sync(0xffffffffu, act, 2);
            float og = __shfl_sync(0xffffffffu, act, 3);
            if (lane == 0) {
                float c = fmaf(fg, creg, act * gg);
                float e2 = __expf(-2.0f * c);
                float th = fmaf(2.0f, __fdividef(1.0f, 1.0f + e2), -1.0f);
                float h = og * th;
                creg = c; hreg = h;
                store_tag(ownB + t * H + u, h, t);
            }
            // one barrier/step: sIn double-buffered by t parity.
        }
        return;
    }

    // ============================ ATTENTION + MLP ============================
    // 512 threads; upper 256 duplicate lower 256's compute (benign), writes
    // guarded. Algorithm identical to R10 (2 steps per block).
    int ht = tid & 255;
    int laneh = ht & 31, warph = ht >> 5;
    int t0 = (blockIdx.x - RNN_BLOCKS) * 2;
    bool wr0 = (tid < 256);

    if (wr0) {
        avs[ht] = attVec[ht];
        h2s[0][ht] = poll_tag_sleep(&g_Ht64[2 * LSTRIDE + (t0 + 1) * H + ht], (unsigned)(t0 + 1));
        h2s[1][ht] = poll_tag_sleep(&g_Ht64[2 * LSTRIDE + (t0 + 2) * H + ht], (unsigned)(t0 + 2));
    }
    __syncthreads();

    {
        float s0 = 0.f, s1 = 0.f;
        const float4* wr = (const float4*)(attW + ht * H);
        const float4* x0 = (const float4*)h2s[0];
        const float4* x1 = (const float4*)h2s[1];
#pragma unroll 8
        for (int k = 0; k < 64; k++) {
            float4 w = wr[k], a = x0[k], b = x1[k];
            s0 += w.x * a.x + w.y * a.y + w.z * a.z + w.w * a.w;
            s1 += w.x * b.x + w.y * b.y + w.z * b.z + w.w * b.w;
        }
        if (wr0) { wss[0][ht] = s0; wss[1][ht] = s1; }
    }
    __syncthreads();

    float e00 = 0.f, e01 = 0.f, e02 = 0.f, e03 = 0.f;
    float e10 = 0.f, e11 = 0.f, e12 = 0.f, e13 = 0.f;
    const float4* vb = (const float4*)g_VOutB;
#pragma unroll 4
    for (int h = 0; h < H; h++) {
        float a = avs[h], w0v = wss[0][h], w1v = wss[1][h];
        float4 v4 = vb[h * (SENC / 4) + ht];
        e00 = fmaf(a, tanh_poly(w0v + v4.x), e00);
        e01 = fmaf(a, tanh_poly(w0v + v4.y), e01);
        e02 = fmaf(a, tanh_poly(w0v + v4.z), e02);
        e03 = fmaf(a, tanh_poly(w0v + v4.w), e03);
        e10 = fmaf(a, tanh_poly(w1v + v4.x), e10);
        e11 = fmaf(a, tanh_poly(w1v + v4.y), e11);
        e12 = fmaf(a, tanh_poly(w1v + v4.z), e12);
        e13 = fmaf(a, tanh_poly(w1v + v4.w), e13);
    }

    float mx0 = fmaxf(fmaxf(e00, e01), fmaxf(e02, e03));
    float mx1 = fmaxf(fmaxf(e10, e11), fmaxf(e12, e13));
#pragma unroll
    for (int off = 16; off > 0; off >>= 1) {
        mx0 = fmaxf(mx0, __shfl_xor_sync(0xffffffffu, mx0, off));
        mx1 = fmaxf(mx1, __shfl_xor_sync(0xffffffffu, mx1, off));
    }
    if (wr0 && laneh == 0) { red[warph] = mx0; red[8 + warph] = mx1; }
    __syncthreads();
    if (tid == 0) {
        float m0 = red[0], m1 = red[8];
#pragma unroll
        for (int i = 1; i < 8; i++) { m0 = fmaxf(m0, red[i]); m1 = fmaxf(m1, red[8 + i]); }
        red[32] = m0; red[33] = m1;
    }
    __syncthreads();
    mx0 = red[32]; mx1 = red[33];
    float x00 = __expf(e00 - mx0), x01 = __expf(e01 - mx0);
    float x02 = __expf(e02 - mx0), x03 = __expf(e03 - mx0);
    float x10 = __expf(e10 - mx1), x11 = __expf(e11 - mx1);
    float x12 = __expf(e12 - mx1), x13 = __expf(e13 - mx1);
    float sm0 = x00 + x01 + x02 + x03;
    float sm1 = x10 + x11 + x12 + x13;
#pragma unroll
    for (int off = 16; off > 0; off >>= 1) {
        sm0 += __shfl_xor_sync(0xffffffffu, sm0, off);
        sm1 += __shfl_xor_sync(0xffffffffu, sm1, off);
    }
    if (wr0 && laneh == 0) { red[16 + warph] = sm0; red[24 + warph] = sm1; }
    __syncthreads();
    if (tid == 0) {
        float s0 = 0.f, s1 = 0.f;
#pragma unroll
        for (int i = 0; i < 8; i++) { s0 += red[16 + i]; s1 += red[24 + i]; }
        red[34] = 1.0f / s0;
        red[35] = 1.0f / s1;
    }
    __syncthreads();
    float inv0 = red[34], inv1 = red[35];
    if (wr0) {
        alp[0][4 * ht + 0] = x00 * inv0; alp[0][4 * ht + 1] = x01 * inv0;
        alp[0][4 * ht + 2] = x02 * inv0; alp[0][4 * ht + 3] = x03 * inv0;
        alp[1][4 * ht + 0] = x10 * inv1; alp[1][4 * ht + 1] = x11 * inv1;
        alp[1][4 * ht + 2] = x12 * inv1; alp[1][4 * ht + 3] = x13 * inv1;
    }
    __syncthreads();

    float c0v = 0.f, c1v = 0.f;
#pragma unroll 4
    for (int s = 0; s < SENC; s++) {
        float v = __ldg(&outEnc[s * H + ht]);
        c0v = fmaf(alp[0][s], v, c0v);
        c1v = fmaf(alp[1][s], v, c1v);
    }
    if (wr0) {
        vbuf[0][ht] = h2s[0][ht]; vbuf[0][H + ht] = c0v;
        vbuf[1][ht] = h2s[1][ht]; vbuf[1][H + ht] = c1v;
    }
    __syncthreads();

    {
        float s0 = b1[ht], s1 = s0;
        const float4* r = (const float4*)(w1 + ht * (2 * H));
        const float4* xa = (const float4*)vbuf[0];
        const float4* xb = (const float4*)vbuf[1];
#pragma unroll 8
        for (int k = 0; k < 128; k++) {
            float4 w = r[k], a = xa[k], b = xb[k];
            s0 += w.x * a.x + w.y * a.y + w.z * a.z + w.w * a.w;
            s1 += w.x * b.x + w.y * b.y + w.z * b.z + w.w * b.w;
        }
        if (wr0) { v1s[0][ht] = fmaxf(s0, 0.f); v1s[1][ht] = fmaxf(s1, 0.f); }
    }
    __syncthreads();
    {
        float s0 = b2[ht], s1 = s0;
        const float4* r = (const float4*)(w2 + ht * H);
        const float4* xa = (const float4*)v1s[0];
        const float4* xb = (const float4*)v1s[1];
#pragma unroll 8
        for (int k = 0; k < 64; k++) {
            float4 w = r[k], a = xa[k], b = xb[k];
            s0 += w.x * a.x + w.y * a.y + w.z * a.z + w.w * a.w;
            s1 += w.x * b.x + w.y * b.y + w.z * b.z + w.w * b.w;
        }
        if (wr0) { v2s[0][ht] = fmaxf(s0, 0.f); v2s[1][ht] = fmaxf(s1, 0.f); }
    }
    __syncthreads();
    if (wr0 && ht < VOCAB) {
        float s0 = b3[ht], s1 = s0;
        const float4* r = (const float4*)(w3 + ht * H);
        const float4* xa = (const float4*)v2s[0];
        const float4* xb = (const float4*)v2s[1];
#pragma unroll 8
        for (int k = 0; k < 64; k++) {
            float4 w = r[k], a = xa[k], b = xb[k];
            s0 += w.x * a.x + w.y * a.y + w.z * a.z + w.w * a.w;
            s1 += w.x * b.x + w.y * b.y + w.z * b.z + w.w * b.w;
        }
        outp[(t0 + 0) * VOCAB + ht] = s0;
        outp[(t0 + 1) * VOCAB + ht] = s1;
    }
}

extern "C" void kernel_launch(void* const* d_in, const int* in_sizes, int n_in,
                              void* d_out, int out_size) {
    const int*   Y      = (const int*)d_in[0];
    const float* h0     = (const float*)d_in[1];
    const float* c0     = (const float*)d_in[2];
    const float* outEnc = (const float*)d_in[3];
    const float* emb    = (const float*)d_in[4];
    const float* W_ih1  = (const float*)d_in[5];
    const float* W_hh1  = (const float*)d_in[6];
    const float* b_ih1  = (const float*)d_in[7];
    const float* b_hh1  = (const float*)d_in[8];
    const float* W_ih2  = (const float*)d_in[9];
    const float* W_hh2  = (const float*)d_in[10];
    const float* b_ih2  = (const float*)d_in[11];
    const float* b_hh2  = (const float*)d_in[12];
    const float* W_ih3  = (const float*)d_in[13];
    const float* W_hh3  = (const float*)d_in[14];
    const float* b_ih3  = (const float*)d_in[15];
    const float* b_hh3  = (const float*)d_in[16];
    const float* attVec = (const float*)d_in[17];
    const float* attW   = (const float*)d_in[18];
    const float* attV   = (const float*)d_in[19];
    const float* attB   = (const float*)d_in[20];
    const float* w1     = (const float*)d_in[21];
    const float* b1     = (const float*)d_in[22];
    const float* w2     = (const float*)d_in[23];
    const float* b2     = (const float*)d_in[24];
    const float* w3     = (const float*)d_in[25];
    const float* b3     = (const float*)d_in[26];
    float* outp = (float*)d_out;

    prep_kernel<<<520, 256>>>(Y, h0, emb, W_ih1, b_ih1, b_hh1, attV, attB, outEnc);
    fused_kernel<<<RNN_BLOCKS + ATTN_BLOCKS, NTHREADS>>>(
        h0, c0, W_ih2, W_hh2, b_ih2, b_hh2, W_ih3, W_hh3, b_ih3, b_hh3, W_hh1,
        outEnc, attW, attVec, w1, b1, w2, b2, w3, b3, outp);
}